// round 6
// baseline (speedup 1.0000x reference)
#include <cuda_runtime.h>
#include <math.h>

#define Bn 16
#define Tn 12
#define Nn 325
#define Fn 64
#define KHn 4
#define Dn 16
#define KDn 3
#define BTn (Bn*Tn)            // 192
#define BTNn (BTn*Nn)          // 62400
#define NNn (Nn*Nn)            // 105625

// ---------------- scratch (device globals; no allocation allowed) ----------------
__device__ float g_q [KHn*BTNn*Dn + 16];
__device__ float g_k [KHn*BTNn*Dn + 16];
__device__ float g_ks[KHn*BTNn*Dn + 16];
__device__ float g_v [KHn*BTNn*Dn + 16];
__device__ float g_vs[KHn*BTNn*Dn + 16];
__device__ float g_biasT[KHn*NNn + 2048];   // transposed [h][m][n]
__device__ float g_val[BTNn*Fn];

// ---------------- kernel 1: graph-diffusion bias, transposed output ----------------
__global__ void bias_kernel(const float* __restrict__ A, const float* __restrict__ AT,
                            const float* __restrict__ Wdi, const float* __restrict__ Wdo)
{
    __shared__ float tile[32][33];
    int h = blockIdx.z;
    int n0 = blockIdx.x*32, m0 = blockIdx.y*32;
    int tx = threadIdx.x, ty = threadIdx.y;    // 32 x 8

#pragma unroll
    for (int k = 0; k < 4; ++k) {
        int n = n0 + ty + 8*k, m = m0 + tx;
        float s = 0.f;
        if (n < Nn && m < Nn) {
            int nm = n*Nn + m;
            if (h < 2) {
#pragma unroll
                for (int j = 0; j < KDn; ++j) s = fmaf(Wdi[(h*KDn+j)*NNn+nm], A[j*NNn+nm], s);
            } else {
#pragma unroll
                for (int j = 0; j < KDn; ++j) s = fmaf(Wdo[((h-2)*KDn+j)*NNn+nm], AT[j*NNn+nm], s);
            }
        }
        tile[ty + 8*k][tx] = s;
    }
    __syncthreads();
#pragma unroll
    for (int k = 0; k < 4; ++k) {
        int m = m0 + ty + 8*k, n = n0 + tx;
        if (m < Nn && n < Nn)
            g_biasT[(size_t)h*NNn + (size_t)m*Nn + n] = tile[tx][ty + 8*k];
    }
}

// ---------------- kernel 2: projection (grid.y selects which of the 5) ----------------
__global__ __launch_bounds__(256) void proj_kernel(
    const float* __restrict__ x,
    const float* __restrict__ Wq,  const float* __restrict__ bq,
    const float* __restrict__ Wk,  const float* __restrict__ bk,
    const float* __restrict__ Wks, const float* __restrict__ bks,
    const float* __restrict__ Wv,  const float* __restrict__ bv,
    const float* __restrict__ Wvs, const float* __restrict__ bvs)
{
    extern __shared__ float sm[];
    float* sW   = sm;                 // 64*68 = 4352
    float* sb   = sm + 4352;          // 64
    float* srow = sm + 4416;          // 8 warps * 512 = 4096

    int p = blockIdx.y;
    const float* W = (p==0)?Wq:(p==1)?Wk:(p==2)?Wks:(p==3)?Wv:Wvs;
    const float* bb = (p==0)?bq:(p==1)?bk:(p==2)?bks:(p==3)?bv:bvs;
    float* o = (p==0)?g_q:(p==1)?g_k:(p==2)?g_ks:(p==3)?g_v:g_vs;

    for (int i = threadIdx.x; i < 4096; i += 256) {
        int f = i >> 6, c = i & 63;
        sW[f*68 + c] = W[i];
    }
    if (threadIdx.x < 64) sb[threadIdx.x] = bb[threadIdx.x];

    int warp = threadIdx.x >> 5, lane = threadIdx.x & 31;
    int r0 = blockIdx.x * 64 + warp * 8;
    float* myrow = srow + warp*512;
    {
        const float* xs = x + (size_t)r0*64;
        for (int i = lane; i < 512; i += 32) myrow[i] = xs[i];
    }
    __syncthreads();

    int f0 = lane, f1 = lane + 32;
    int h0 = f0 >> 4, d0 = f0 & 15;
    int h1 = f1 >> 4, d1 = f1 & 15;

    float acc0[8], acc1[8];
    float bb0 = sb[f0], bb1 = sb[f1];
#pragma unroll
    for (int r = 0; r < 8; ++r) { acc0[r] = bb0; acc1[r] = bb1; }
#pragma unroll 4
    for (int c = 0; c < 64; c += 4) {
        float4 w0 = *(const float4*)(sW + f0*68 + c);
        float4 w1 = *(const float4*)(sW + f1*68 + c);
#pragma unroll
        for (int r = 0; r < 8; ++r) {
            float4 xv = *(const float4*)(myrow + r*64 + c);
            acc0[r] = fmaf(xv.x, w0.x, acc0[r]);
            acc1[r] = fmaf(xv.x, w1.x, acc1[r]);
            acc0[r] = fmaf(xv.y, w0.y, acc0[r]);
            acc1[r] = fmaf(xv.y, w1.y, acc1[r]);
            acc0[r] = fmaf(xv.z, w0.z, acc0[r]);
            acc1[r] = fmaf(xv.z, w1.z, acc1[r]);
            acc0[r] = fmaf(xv.w, w0.w, acc0[r]);
            acc1[r] = fmaf(xv.w, w1.w, acc1[r]);
        }
    }
#pragma unroll
    for (int r = 0; r < 8; ++r) {
        size_t rr = (size_t)(r0 + r);
        o[((size_t)h0*BTNn + rr)*Dn + d0] = acc0[r];
        o[((size_t)h1*BTNn + rr)*Dn + d1] = acc1[r];
    }
}

// ---------------- kernel 3: attention (thread per query, bias double-buffered) ----------------
#define ATH 352
__global__ __launch_bounds__(ATH) void attn_kernel()
{
    extern __shared__ float sm[];
    float* sk = sm;              // 325*16 = 5200
    float* sv = sm + 5200;       // 5200

    int bt = blockIdx.x, h = blockIdx.y;
    size_t base = ((size_t)h*BTNn + (size_t)bt*Nn)*Dn;

    {
        const float4* kb = (const float4*)(g_k + base);
        const float4* vb = (const float4*)(g_v + base);
        float4* k4 = (float4*)sk;
        float4* v4 = (float4*)sv;
        for (int i = threadIdx.x; i < Nn*Dn/4; i += ATH) {
            k4[i] = kb[i];
            v4[i] = vb[i];
        }
    }
    __syncthreads();

    int n = threadIdx.x;
    if (n >= Nn) return;

    float q[16], o[16];
    float l = 0.f;
    float es;
    {
        const float4* qp = (const float4*)(g_q  + base + (size_t)n*Dn);
        const float4* kp = (const float4*)(g_ks + base + (size_t)n*Dn);
        float s = 0.f;
#pragma unroll
        for (int i = 0; i < 4; ++i) {
            float4 qv = qp[i], kv = kp[i];
            q[i*4+0]=qv.x; q[i*4+1]=qv.y; q[i*4+2]=qv.z; q[i*4+3]=qv.w;
            s = fmaf(qv.x,kv.x, fmaf(qv.y,kv.y, fmaf(qv.z,kv.z, fmaf(qv.w,kv.w, s))));
        }
        es = 1.f/(1.f + __expf(-s*0.25f));
#pragma unroll
        for (int d = 0; d < 16; ++d) o[d] = 0.f;
    }

    const float* bT = g_biasT + (size_t)h*NNn + n;

#define KEYSTEP(mm, bval) { \
        const float4* kr = (const float4*)(sk + (mm)*16); \
        float4 k0 = kr[0], k1 = kr[1], k2 = kr[2], k3 = kr[3]; \
        float s; \
        s  = q[0]*k0.x;             s = fmaf(q[1],k0.y,s); \
        s = fmaf(q[2],k0.z,s);      s = fmaf(q[3],k0.w,s); \
        s = fmaf(q[4],k1.x,s);      s = fmaf(q[5],k1.y,s); \
        s = fmaf(q[6],k1.z,s);      s = fmaf(q[7],k1.w,s); \
        s = fmaf(q[8],k2.x,s);      s = fmaf(q[9],k2.y,s); \
        s = fmaf(q[10],k2.z,s);     s = fmaf(q[11],k2.w,s); \
        s = fmaf(q[12],k3.x,s);     s = fmaf(q[13],k3.y,s); \
        s = fmaf(q[14],k3.z,s);     s = fmaf(q[15],k3.w,s); \
        float e = fmaf(s, 0.25f, (bval)); \
        float p = __expf(e); \
        l += p; \
        const float4* vr = (const float4*)(sv + (mm)*16); \
        float4 v0 = vr[0], v1 = vr[1], v2 = vr[2], v3 = vr[3]; \
        o[0]  = fmaf(p, v0.x, o[0]);  o[1]  = fmaf(p, v0.y, o[1]); \
        o[2]  = fmaf(p, v0.z, o[2]);  o[3]  = fmaf(p, v0.w, o[3]); \
        o[4]  = fmaf(p, v1.x, o[4]);  o[5]  = fmaf(p, v1.y, o[5]); \
        o[6]  = fmaf(p, v1.z, o[6]);  o[7]  = fmaf(p, v1.w, o[7]); \
        o[8]  = fmaf(p, v2.x, o[8]);  o[9]  = fmaf(p, v2.y, o[9]); \
        o[10] = fmaf(p, v2.z, o[10]); o[11] = fmaf(p, v2.w, o[11]); \
        o[12] = fmaf(p, v3.x, o[12]); o[13] = fmaf(p, v3.y, o[13]); \
        o[14] = fmaf(p, v3.z, o[14]); o[15] = fmaf(p, v3.w, o[15]); \
    }

    // bias double-buffer: prefetch next 4 keys' bias while computing current 4
    float bc0 = __ldg(bT);
    float bc1 = __ldg(bT + Nn);
    float bc2 = __ldg(bT + 2*Nn);
    float bc3 = __ldg(bT + 3*Nn);
    const float* bp = bT + 4*Nn;
#pragma unroll 1
    for (int g = 0; g < 80; ++g) {
        float bn0 = __ldg(bp);
        float bn1 = __ldg(bp + Nn);
        float bn2 = __ldg(bp + 2*Nn);
        float bn3 = __ldg(bp + 3*Nn);
        bp += 4*Nn;
        int m0 = g*4;
        KEYSTEP(m0+0, bc0);
        KEYSTEP(m0+1, bc1);
        KEYSTEP(m0+2, bc2);
        KEYSTEP(m0+3, bc3);
        bc0 = bn0; bc1 = bn1; bc2 = bn2; bc3 = bn3;
    }
    KEYSTEP(320, bc0);
    KEYSTEP(321, bc1);
    KEYSTEP(322, bc2);
    KEYSTEP(323, bc3);
    {
        float blast = __ldg(bT + (size_t)324*Nn);
        KEYSTEP(324, blast);
    }
#undef KEYSTEP

    {
        float inv = 1.f/(es + l);
        const float4* vsp = (const float4*)(g_vs + base + (size_t)n*Dn);
        float* outp = g_val + ((size_t)bt*Nn + n)*Fn + h*Dn;
#pragma unroll
        for (int i = 0; i < 4; ++i) {
            float4 vs = vsp[i];
            float4 r;
            r.x = fmaf(o[i*4+0] - l*vs.x, inv, vs.x);
            r.y = fmaf(o[i*4+1] - l*vs.y, inv, vs.y);
            r.z = fmaf(o[i*4+2] - l*vs.z, inv, vs.z);
            r.w = fmaf(o[i*4+3] - l*vs.w, inv, vs.w);
            *(float4*)(outp + i*4) = r;
        }
    }
}

// ---------------- kernel 4: FFN(gelu) + residual + LayerNorm ----------------
__global__ __launch_bounds__(256) void ffn_kernel(
    const float* __restrict__ x,
    const float* __restrict__ Wf1, const float* __restrict__ bf1,
    const float* __restrict__ Wf2, const float* __restrict__ bf2,
    const float* __restrict__ gln, const float* __restrict__ bln,
    float* __restrict__ out)
{
    extern __shared__ float sm[];
    float* sW1 = sm;            // 4352
    float* sW2 = sm + 4352;     // 4352
    float* sb1 = sm + 8704;     // 64
    float* sb2 = sm + 8768;     // 64
    float* sg  = sm + 8832;     // 64
    float* sbl = sm + 8896;     // 64
    float* srow = sm + 8960;    // 8 * 512 = 4096

    for (int i = threadIdx.x; i < 4096; i += 256) {
        int f = i >> 6, c = i & 63;
        sW1[f*68+c] = Wf1[i];
        sW2[f*68+c] = Wf2[i];
    }
    if (threadIdx.x < 64) {
        sb1[threadIdx.x] = bf1[threadIdx.x];
        sb2[threadIdx.x] = bf2[threadIdx.x];
        sg [threadIdx.x] = gln[threadIdx.x];
        sbl[threadIdx.x] = bln[threadIdx.x];
    }

    int warp = threadIdx.x >> 5, lane = threadIdx.x & 31;
    int r0 = blockIdx.x*64 + warp*8;
    float* myrow = srow + warp*512;
    {
        const float* vs = g_val + (size_t)r0*64;
        for (int i = lane; i < 512; i += 32) myrow[i] = vs[i];
    }
    __syncthreads();

    int f0 = lane, f1 = lane + 32;
    float t0[8], t1[8];
#pragma unroll
    for (int r = 0; r < 8; ++r) { t0[r] = sb1[f0]; t1[r] = sb1[f1]; }
#pragma unroll 4
    for (int c = 0; c < 64; c += 4) {
        float4 w0 = *(const float4*)(sW1 + f0*68 + c);
        float4 w1 = *(const float4*)(sW1 + f1*68 + c);
#pragma unroll
        for (int r = 0; r < 8; ++r) {
            float4 xv = *(const float4*)(myrow + r*64 + c);
            t0[r] = fmaf(xv.x, w0.x, t0[r]);  t1[r] = fmaf(xv.x, w1.x, t1[r]);
            t0[r] = fmaf(xv.y, w0.y, t0[r]);  t1[r] = fmaf(xv.y, w1.y, t1[r]);
            t0[r] = fmaf(xv.z, w0.z, t0[r]);  t1[r] = fmaf(xv.z, w1.z, t1[r]);
            t0[r] = fmaf(xv.w, w0.w, t0[r]);  t1[r] = fmaf(xv.w, w1.w, t1[r]);
        }
    }
    // exact gelu
#pragma unroll
    for (int r = 0; r < 8; ++r) {
        t0[r] = 0.5f*t0[r]*(1.f + erff(t0[r]*0.7071067811865476f));
        t1[r] = 0.5f*t1[r]*(1.f + erff(t1[r]*0.7071067811865476f));
    }
    __syncwarp();
#pragma unroll
    for (int r = 0; r < 8; ++r) { myrow[r*64+f0] = t0[r]; myrow[r*64+f1] = t1[r]; }
    __syncwarp();

    float h0[8], h1[8];
    const float* xr = x + (size_t)r0*64;
#pragma unroll
    for (int r = 0; r < 8; ++r) {
        h0[r] = sb2[f0] + xr[r*64+f0];
        h1[r] = sb2[f1] + xr[r*64+f1];
    }
#pragma unroll 4
    for (int c = 0; c < 64; c += 4) {
        float4 w0 = *(const float4*)(sW2 + f0*68 + c);
        float4 w1 = *(const float4*)(sW2 + f1*68 + c);
#pragma unroll
        for (int r = 0; r < 8; ++r) {
            float4 xv = *(const float4*)(myrow + r*64 + c);
            h0[r] = fmaf(xv.x, w0.x, h0[r]);  h1[r] = fmaf(xv.x, w1.x, h1[r]);
            h0[r] = fmaf(xv.y, w0.y, h0[r]);  h1[r] = fmaf(xv.y, w1.y, h1[r]);
            h0[r] = fmaf(xv.z, w0.z, h0[r]);  h1[r] = fmaf(xv.z, w1.z, h1[r]);
            h0[r] = fmaf(xv.w, w0.w, h0[r]);  h1[r] = fmaf(xv.w, w1.w, h1[r]);
        }
    }
#pragma unroll
    for (int r = 0; r < 8; ++r) {
        float s1 = h0[r] + h1[r];
        float s2 = fmaf(h0[r], h0[r], h1[r]*h1[r]);
#pragma unroll
        for (int oo = 16; oo; oo >>= 1) {
            s1 += __shfl_xor_sync(0xffffffffu, s1, oo);
            s2 += __shfl_xor_sync(0xffffffffu, s2, oo);
        }
        float mean = s1 * (1.f/64.f);
        float var  = s2 * (1.f/64.f) - mean*mean;
        float rs   = rsqrtf(var + 1e-5f);
        out[(size_t)(r0+r)*64 + f0] = fmaf(sg[f0], (h0[r]-mean)*rs, sbl[f0]);
        out[(size_t)(r0+r)*64 + f1] = fmaf(sg[f1], (h1[r]-mean)*rs, sbl[f1]);
    }
}

// ---------------- launch ----------------
extern "C" void kernel_launch(void* const* d_in, const int* in_sizes, int n_in,
                              void* d_out, int out_size)
{
    const float* x   = (const float*)d_in[0];
    const float* A   = (const float*)d_in[1];
    const float* AT  = (const float*)d_in[2];
    const float* Wq  = (const float*)d_in[3];
    const float* bq  = (const float*)d_in[4];
    const float* Wk  = (const float*)d_in[5];
    const float* bk  = (const float*)d_in[6];
    const float* Wks = (const float*)d_in[7];
    const float* bks = (const float*)d_in[8];
    const float* Wv  = (const float*)d_in[9];
    const float* bv  = (const float*)d_in[10];
    const float* Wvs = (const float*)d_in[11];
    const float* bvs = (const float*)d_in[12];
    const float* Wdi = (const float*)d_in[13];
    const float* Wdo = (const float*)d_in[14];
    const float* Wf1 = (const float*)d_in[15];
    const float* bf1 = (const float*)d_in[16];
    const float* Wf2 = (const float*)d_in[17];
    const float* bf2 = (const float*)d_in[18];
    const float* gln = (const float*)d_in[19];
    const float* bln = (const float*)d_in[20];
    float* out = (float*)d_out;

    cudaFuncSetAttribute(proj_kernel, cudaFuncAttributeMaxDynamicSharedMemorySize, 34048);
    cudaFuncSetAttribute(attn_kernel, cudaFuncAttributeMaxDynamicSharedMemorySize, 41600);
    cudaFuncSetAttribute(ffn_kernel,  cudaFuncAttributeMaxDynamicSharedMemorySize, 52224);

    dim3 bg(11, 11, 4);
    bias_kernel<<<bg, dim3(32, 8)>>>(A, AT, Wdi, Wdo);
    dim3 pg(975, 5);
    proj_kernel<<<pg, 256, 34048>>>(x, Wq, bq, Wk, bk, Wks, bks, Wv, bv, Wvs, bvs);
    dim3 ag(BTn, KHn);
    attn_kernel<<<ag, ATH, 41600>>>();
    ffn_kernel<<<975, 256, 52224>>>(x, Wf1, bf1, Wf2, bf2, gln, bln, out);
}

// round 7
// speedup vs baseline: 1.1474x; 1.1474x over previous
#include <cuda_runtime.h>
#include <math.h>

#define Bn 16
#define Tn 12
#define Nn 325
#define Fn 64
#define KHn 4
#define Dn 16
#define KDn 3
#define BTn (Bn*Tn)            // 192
#define BTNn (BTn*Nn)          // 62400
#define NNn (Nn*Nn)            // 105625

// ---------------- scratch (device globals; no allocation allowed) ----------------
__device__ float g_q [KHn*BTNn*Dn + 16];
__device__ float g_k [KHn*BTNn*Dn + 16];
__device__ float g_ks[KHn*BTNn*Dn + 16];
__device__ float g_v [KHn*BTNn*Dn + 16];
__device__ float g_vs[KHn*BTNn*Dn + 16];
__device__ float g_biasT[KHn*NNn + 2048];   // transposed [h][m][n]
__device__ float g_val[BTNn*Fn];

// ---------------- kernel 1: graph-diffusion bias, transposed output ----------------
__global__ void bias_kernel(const float* __restrict__ A, const float* __restrict__ AT,
                            const float* __restrict__ Wdi, const float* __restrict__ Wdo)
{
    __shared__ float tile[32][33];
    int h = blockIdx.z;
    int n0 = blockIdx.x*32, m0 = blockIdx.y*32;
    int tx = threadIdx.x, ty = threadIdx.y;    // 32 x 8

#pragma unroll
    for (int k = 0; k < 4; ++k) {
        int n = n0 + ty + 8*k, m = m0 + tx;
        float s = 0.f;
        if (n < Nn && m < Nn) {
            int nm = n*Nn + m;
            if (h < 2) {
#pragma unroll
                for (int j = 0; j < KDn; ++j) s = fmaf(Wdi[(h*KDn+j)*NNn+nm], A[j*NNn+nm], s);
            } else {
#pragma unroll
                for (int j = 0; j < KDn; ++j) s = fmaf(Wdo[((h-2)*KDn+j)*NNn+nm], AT[j*NNn+nm], s);
            }
        }
        tile[ty + 8*k][tx] = s;
    }
    __syncthreads();
#pragma unroll
    for (int k = 0; k < 4; ++k) {
        int m = m0 + ty + 8*k, n = n0 + tx;
        if (m < Nn && n < Nn)
            g_biasT[(size_t)h*NNn + (size_t)m*Nn + n] = tile[tx][ty + 8*k];
    }
}

// ---------------- kernel 2: projection (persistent; grid (148,5)) ----------------
// Weights loaded into smem ONCE per block; loop over row-chunks with no block syncs
// (srow is warp-private, __syncwarp only).
__global__ __launch_bounds__(256) void proj_kernel(
    const float* __restrict__ x,
    const float* __restrict__ Wq,  const float* __restrict__ bq,
    const float* __restrict__ Wk,  const float* __restrict__ bk,
    const float* __restrict__ Wks, const float* __restrict__ bks,
    const float* __restrict__ Wv,  const float* __restrict__ bv,
    const float* __restrict__ Wvs, const float* __restrict__ bvs)
{
    extern __shared__ float sm[];
    float* sW   = sm;                 // 64*68 = 4352
    float* sb   = sm + 4352;          // 64
    float* srow = sm + 4416;          // 8 warps * 512 = 4096

    int p = blockIdx.y;
    const float* W = (p==0)?Wq:(p==1)?Wk:(p==2)?Wks:(p==3)?Wv:Wvs;
    const float* bb = (p==0)?bq:(p==1)?bk:(p==2)?bks:(p==3)?bv:bvs;
    float* o = (p==0)?g_q:(p==1)?g_k:(p==2)?g_ks:(p==3)?g_v:g_vs;

    for (int i = threadIdx.x; i < 4096; i += 256) {
        int f = i >> 6, c = i & 63;
        sW[f*68 + c] = W[i];
    }
    if (threadIdx.x < 64) sb[threadIdx.x] = bb[threadIdx.x];
    __syncthreads();

    int warp = threadIdx.x >> 5, lane = threadIdx.x & 31;
    float* myrow = srow + warp*512;
    int f0 = lane, f1 = lane + 32;
    int h0 = f0 >> 4, d0 = f0 & 15;
    int h1 = f1 >> 4, d1 = f1 & 15;
    float bb0 = sb[f0], bb1 = sb[f1];

    for (int blk = blockIdx.x; blk < 975; blk += 148) {
        int r0 = blk * 64 + warp * 8;
        {
            const float* xs = x + (size_t)r0*64;
            for (int i = lane; i < 512; i += 32) myrow[i] = xs[i];
        }
        __syncwarp();

        float acc0[8], acc1[8];
#pragma unroll
        for (int r = 0; r < 8; ++r) { acc0[r] = bb0; acc1[r] = bb1; }
#pragma unroll 4
        for (int c = 0; c < 64; c += 4) {
            float4 w0 = *(const float4*)(sW + f0*68 + c);
            float4 w1 = *(const float4*)(sW + f1*68 + c);
#pragma unroll
            for (int r = 0; r < 8; ++r) {
                float4 xv = *(const float4*)(myrow + r*64 + c);
                acc0[r] = fmaf(xv.x, w0.x, acc0[r]);
                acc1[r] = fmaf(xv.x, w1.x, acc1[r]);
                acc0[r] = fmaf(xv.y, w0.y, acc0[r]);
                acc1[r] = fmaf(xv.y, w1.y, acc1[r]);
                acc0[r] = fmaf(xv.z, w0.z, acc0[r]);
                acc1[r] = fmaf(xv.z, w1.z, acc1[r]);
                acc0[r] = fmaf(xv.w, w0.w, acc0[r]);
                acc1[r] = fmaf(xv.w, w1.w, acc1[r]);
            }
        }
#pragma unroll
        for (int r = 0; r < 8; ++r) {
            size_t rr = (size_t)(r0 + r);
            o[((size_t)h0*BTNn + rr)*Dn + d0] = acc0[r];
            o[((size_t)h1*BTNn + rr)*Dn + d1] = acc1[r];
        }
        __syncwarp();
    }
}

// ---------------- kernel 3: attention (thread per query; 3 blocks/SM) ----------------
#define ATH 352
__global__ __launch_bounds__(ATH, 3) void attn_kernel()
{
    extern __shared__ float sm[];
    float* sk = sm;              // 325*16 = 5200
    float* sv = sm + 5200;       // 5200

    int bt = blockIdx.x, h = blockIdx.y;
    size_t base = ((size_t)h*BTNn + (size_t)bt*Nn)*Dn;

    {
        const float4* kb = (const float4*)(g_k + base);
        const float4* vb = (const float4*)(g_v + base);
        float4* k4 = (float4*)sk;
        float4* v4 = (float4*)sv;
        for (int i = threadIdx.x; i < Nn*Dn/4; i += ATH) {
            k4[i] = kb[i];
            v4[i] = vb[i];
        }
    }
    __syncthreads();

    int n = threadIdx.x;
    if (n >= Nn) return;

    float q[16], o[16];
    float l = 0.f;
    float es;
    {
        const float4* qp = (const float4*)(g_q  + base + (size_t)n*Dn);
        const float4* kp = (const float4*)(g_ks + base + (size_t)n*Dn);
        float s = 0.f;
#pragma unroll
        for (int i = 0; i < 4; ++i) {
            float4 qv = qp[i], kv = kp[i];
            q[i*4+0]=qv.x; q[i*4+1]=qv.y; q[i*4+2]=qv.z; q[i*4+3]=qv.w;
            s = fmaf(qv.x,kv.x, fmaf(qv.y,kv.y, fmaf(qv.z,kv.z, fmaf(qv.w,kv.w, s))));
        }
        es = 1.f/(1.f + __expf(-s*0.25f));
#pragma unroll
        for (int d = 0; d < 16; ++d) o[d] = 0.f;
    }

    const float* bT = g_biasT + (size_t)h*NNn + n;

#pragma unroll 5
    for (int m = 0; m < Nn; ++m) {
        float bval = __ldg(bT + (size_t)m*Nn);
        const float4* kr = (const float4*)(sk + m*16);
        float4 k0 = kr[0], k1 = kr[1], k2 = kr[2], k3 = kr[3];
        float s;
        s  = q[0]*k0.x;             s = fmaf(q[1],k0.y,s);
        s = fmaf(q[2],k0.z,s);      s = fmaf(q[3],k0.w,s);
        s = fmaf(q[4],k1.x,s);      s = fmaf(q[5],k1.y,s);
        s = fmaf(q[6],k1.z,s);      s = fmaf(q[7],k1.w,s);
        s = fmaf(q[8],k2.x,s);      s = fmaf(q[9],k2.y,s);
        s = fmaf(q[10],k2.z,s);     s = fmaf(q[11],k2.w,s);
        s = fmaf(q[12],k3.x,s);     s = fmaf(q[13],k3.y,s);
        s = fmaf(q[14],k3.z,s);     s = fmaf(q[15],k3.w,s);
        float e = fmaf(s, 0.25f, bval);
        float p = __expf(e);
        l += p;
        const float4* vr = (const float4*)(sv + m*16);
        float4 v0 = vr[0], v1 = vr[1], v2 = vr[2], v3 = vr[3];
        o[0]  = fmaf(p, v0.x, o[0]);  o[1]  = fmaf(p, v0.y, o[1]);
        o[2]  = fmaf(p, v0.z, o[2]);  o[3]  = fmaf(p, v0.w, o[3]);
        o[4]  = fmaf(p, v1.x, o[4]);  o[5]  = fmaf(p, v1.y, o[5]);
        o[6]  = fmaf(p, v1.z, o[6]);  o[7]  = fmaf(p, v1.w, o[7]);
        o[8]  = fmaf(p, v2.x, o[8]);  o[9]  = fmaf(p, v2.y, o[9]);
        o[10] = fmaf(p, v2.z, o[10]); o[11] = fmaf(p, v2.w, o[11]);
        o[12] = fmaf(p, v3.x, o[12]); o[13] = fmaf(p, v3.y, o[13]);
        o[14] = fmaf(p, v3.z, o[14]); o[15] = fmaf(p, v3.w, o[15]);
    }

    {
        float inv = 1.f/(es + l);
        const float4* vsp = (const float4*)(g_vs + base + (size_t)n*Dn);
        float* outp = g_val + ((size_t)bt*Nn + n)*Fn + h*Dn;
#pragma unroll
        for (int i = 0; i < 4; ++i) {
            float4 vs = vsp[i];
            float4 r;
            r.x = fmaf(o[i*4+0] - l*vs.x, inv, vs.x);
            r.y = fmaf(o[i*4+1] - l*vs.y, inv, vs.y);
            r.z = fmaf(o[i*4+2] - l*vs.z, inv, vs.z);
            r.w = fmaf(o[i*4+3] - l*vs.w, inv, vs.w);
            *(float4*)(outp + i*4) = r;
        }
    }
}

// ---------------- kernel 4: FFN(gelu) + residual + LayerNorm (persistent, grid 444) ----------------
__global__ __launch_bounds__(256) void ffn_kernel(
    const float* __restrict__ x,
    const float* __restrict__ Wf1, const float* __restrict__ bf1,
    const float* __restrict__ Wf2, const float* __restrict__ bf2,
    const float* __restrict__ gln, const float* __restrict__ bln,
    float* __restrict__ out)
{
    extern __shared__ float sm[];
    float* sW1 = sm;            // 4352
    float* sW2 = sm + 4352;     // 4352
    float* sb1 = sm + 8704;     // 64
    float* sb2 = sm + 8768;     // 64
    float* sg  = sm + 8832;     // 64
    float* sbl = sm + 8896;     // 64
    float* srow = sm + 8960;    // 8 * 512 = 4096

    for (int i = threadIdx.x; i < 4096; i += 256) {
        int f = i >> 6, c = i & 63;
        sW1[f*68+c] = Wf1[i];
        sW2[f*68+c] = Wf2[i];
    }
    if (threadIdx.x < 64) {
        sb1[threadIdx.x] = bf1[threadIdx.x];
        sb2[threadIdx.x] = bf2[threadIdx.x];
        sg [threadIdx.x] = gln[threadIdx.x];
        sbl[threadIdx.x] = bln[threadIdx.x];
    }
    __syncthreads();

    int warp = threadIdx.x >> 5, lane = threadIdx.x & 31;
    float* myrow = srow + warp*512;
    int f0 = lane, f1 = lane + 32;

    for (int blk = blockIdx.x; blk < 975; blk += 444) {
        int r0 = blk*64 + warp*8;
        {
            const float* vs = g_val + (size_t)r0*64;
            for (int i = lane; i < 512; i += 32) myrow[i] = vs[i];
        }
        __syncwarp();

        float t0[8], t1[8];
#pragma unroll
        for (int r = 0; r < 8; ++r) { t0[r] = sb1[f0]; t1[r] = sb1[f1]; }
#pragma unroll 4
        for (int c = 0; c < 64; c += 4) {
            float4 w0 = *(const float4*)(sW1 + f0*68 + c);
            float4 w1 = *(const float4*)(sW1 + f1*68 + c);
#pragma unroll
            for (int r = 0; r < 8; ++r) {
                float4 xv = *(const float4*)(myrow + r*64 + c);
                t0[r] = fmaf(xv.x, w0.x, t0[r]);  t1[r] = fmaf(xv.x, w1.x, t1[r]);
                t0[r] = fmaf(xv.y, w0.y, t0[r]);  t1[r] = fmaf(xv.y, w1.y, t1[r]);
                t0[r] = fmaf(xv.z, w0.z, t0[r]);  t1[r] = fmaf(xv.z, w1.z, t1[r]);
                t0[r] = fmaf(xv.w, w0.w, t0[r]);  t1[r] = fmaf(xv.w, w1.w, t1[r]);
            }
        }
        // exact gelu
#pragma unroll
        for (int r = 0; r < 8; ++r) {
            t0[r] = 0.5f*t0[r]*(1.f + erff(t0[r]*0.7071067811865476f));
            t1[r] = 0.5f*t1[r]*(1.f + erff(t1[r]*0.7071067811865476f));
        }
        __syncwarp();
#pragma unroll
        for (int r = 0; r < 8; ++r) { myrow[r*64+f0] = t0[r]; myrow[r*64+f1] = t1[r]; }
        __syncwarp();

        float h0[8], h1[8];
        const float* xr = x + (size_t)r0*64;
#pragma unroll
        for (int r = 0; r < 8; ++r) {
            h0[r] = sb2[f0] + xr[r*64+f0];
            h1[r] = sb2[f1] + xr[r*64+f1];
        }
#pragma unroll 4
        for (int c = 0; c < 64; c += 4) {
            float4 w0 = *(const float4*)(sW2 + f0*68 + c);
            float4 w1 = *(const float4*)(sW2 + f1*68 + c);
#pragma unroll
            for (int r = 0; r < 8; ++r) {
                float4 xv = *(const float4*)(myrow + r*64 + c);
                h0[r] = fmaf(xv.x, w0.x, h0[r]);  h1[r] = fmaf(xv.x, w1.x, h1[r]);
                h0[r] = fmaf(xv.y, w0.y, h0[r]);  h1[r] = fmaf(xv.y, w1.y, h1[r]);
                h0[r] = fmaf(xv.z, w0.z, h0[r]);  h1[r] = fmaf(xv.z, w1.z, h1[r]);
                h0[r] = fmaf(xv.w, w0.w, h0[r]);  h1[r] = fmaf(xv.w, w1.w, h1[r]);
            }
        }
#pragma unroll
        for (int r = 0; r < 8; ++r) {
            float s1 = h0[r] + h1[r];
            float s2 = fmaf(h0[r], h0[r], h1[r]*h1[r]);
#pragma unroll
            for (int oo = 16; oo; oo >>= 1) {
                s1 += __shfl_xor_sync(0xffffffffu, s1, oo);
                s2 += __shfl_xor_sync(0xffffffffu, s2, oo);
            }
            float mean = s1 * (1.f/64.f);
            float var  = s2 * (1.f/64.f) - mean*mean;
            float rs   = rsqrtf(var + 1e-5f);
            out[(size_t)(r0+r)*64 + f0] = fmaf(sg[f0], (h0[r]-mean)*rs, sbl[f0]);
            out[(size_t)(r0+r)*64 + f1] = fmaf(sg[f1], (h1[r]-mean)*rs, sbl[f1]);
        }
        __syncwarp();
    }
}

// ---------------- launch ----------------
extern "C" void kernel_launch(void* const* d_in, const int* in_sizes, int n_in,
                              void* d_out, int out_size)
{
    const float* x   = (const float*)d_in[0];
    const float* A   = (const float*)d_in[1];
    const float* AT  = (const float*)d_in[2];
    const float* Wq  = (const float*)d_in[3];
    const float* bq  = (const float*)d_in[4];
    const float* Wk  = (const float*)d_in[5];
    const float* bk  = (const float*)d_in[6];
    const float* Wks = (const float*)d_in[7];
    const float* bks = (const float*)d_in[8];
    const float* Wv  = (const float*)d_in[9];
    const float* bv  = (const float*)d_in[10];
    const float* Wvs = (const float*)d_in[11];
    const float* bvs = (const float*)d_in[12];
    const float* Wdi = (const float*)d_in[13];
    const float* Wdo = (const float*)d_in[14];
    const float* Wf1 = (const float*)d_in[15];
    const float* bf1 = (const float*)d_in[16];
    const float* Wf2 = (const float*)d_in[17];
    const float* bf2 = (const float*)d_in[18];
    const float* gln = (const float*)d_in[19];
    const float* bln = (const float*)d_in[20];
    float* out = (float*)d_out;

    cudaFuncSetAttribute(proj_kernel, cudaFuncAttributeMaxDynamicSharedMemorySize, 34048);
    cudaFuncSetAttribute(attn_kernel, cudaFuncAttributeMaxDynamicSharedMemorySize, 41600);
    cudaFuncSetAttribute(ffn_kernel,  cudaFuncAttributeMaxDynamicSharedMemorySize, 52224);

    dim3 bg(11, 11, 4);
    bias_kernel<<<bg, dim3(32, 8)>>>(A, AT, Wdi, Wdo);
    dim3 pg(148, 5);
    proj_kernel<<<pg, 256, 34048>>>(x, Wq, bq, Wk, bk, Wks, bks, Wv, bv, Wvs, bvs);
    dim3 ag(BTn, KHn);
    attn_kernel<<<ag, ATH, 41600>>>();
    ffn_kernel<<<444, 256, 52224>>>(x, Wf1, bf1, Wf2, bf2, gln, bln, out);
}